// round 16
// baseline (speedup 1.0000x reference)
#include <cuda_runtime.h>
#include <cuda.h>
#include <cuda_fp16.h>
#include <math.h>

// ---- scratch (fp16) ----
__device__ __half g_x[4096*2048];                 // x trunc; reused for ctx
__device__ __half g_w[3072*2048];                 // concat WqT|WkT|WvT trunc
__device__ __half g_wo[2048*2048];
__device__ __half g_q[4096*2048];
__device__ __half g_k[4096*512];
__device__ __half g_v[4096*512];

#define QSCALE (0.125f * 1.4426950408889634f)   // 1/sqrt(64) * log2(e)

__device__ __forceinline__ unsigned packhf(float lo, float hi){
    unsigned r; asm("cvt.rn.f16x2.f32 %0, %1, %2;":"=r"(r):"f"(hi),"f"(lo)); return r;
}

// fp32 -> fp16 truncate
__global__ void __launch_bounds__(256) ftrunc(const float4* __restrict__ in,
                                              uint2* __restrict__ out, int n4){
    int i = blockIdx.x*blockDim.x + threadIdx.x, st = gridDim.x*blockDim.x;
    for(; i < n4; i += st){
        float4 v = in[i];
        uint2 o;
        o.x = packhf(v.x, v.y);
        o.y = packhf(v.z, v.w);
        out[i] = o;
    }
}

// all 4 weights: transpose + fp16 truncate, one launch
__global__ void wtruncAll(const float* __restrict__ Wq, const float* __restrict__ Wk,
                          const float* __restrict__ Wv, const float* __restrict__ Wo,
                          __half* __restrict__ qkv, __half* __restrict__ wo){
    __shared__ float t[32][33];
    int bx = blockIdx.x;
    const float* W; __half *T; int N, n0;
    if(bx < 64){ W=Wq; T=qkv; N=2048; n0=bx*32; }
    else if(bx < 80){ W=Wk; T=qkv+(size_t)2048*2048; N=512; n0=(bx-64)*32; }
    else if(bx < 96){ W=Wv; T=qkv+(size_t)2560*2048; N=512; n0=(bx-80)*32; }
    else { W=Wo; T=wo; N=2048; n0=(bx-96)*32; }
    int k0 = blockIdx.y*32;
    int tx = threadIdx.x, ty = threadIdx.y;
#pragma unroll
    for(int p=0;p<32;p+=8) t[ty+p][tx] = W[(size_t)(k0+ty+p)*N + n0+tx];
    __syncthreads();
#pragma unroll
    for(int p=0;p<32;p+=8)
        T[(size_t)(n0+ty+p)*2048 + k0+tx] = __float2half_rn(t[tx][ty+p]);
}

// ---- helpers ----
__device__ __forceinline__ void ldsm4(unsigned* r, unsigned a){
    asm volatile("ldmatrix.sync.aligned.m8n8.x4.shared.b16 {%0,%1,%2,%3},[%4];"
                 :"=r"(r[0]),"=r"(r[1]),"=r"(r[2]),"=r"(r[3]):"r"(a));
}
__device__ __forceinline__ void ldsm4t(unsigned* r, unsigned a){
    asm volatile("ldmatrix.sync.aligned.m8n8.x4.trans.shared.b16 {%0,%1,%2,%3},[%4];"
                 :"=r"(r[0]),"=r"(r[1]),"=r"(r[2]),"=r"(r[3]):"r"(a));
}
__device__ __forceinline__ void mmaf16(float* c, const unsigned* a, const unsigned* b){
    asm volatile("mma.sync.aligned.m16n8k16.row.col.f32.f16.f16.f32 "
                 "{%0,%1,%2,%3},{%4,%5,%6,%7},{%8,%9},{%0,%1,%2,%3};"
                 :"+f"(c[0]),"+f"(c[1]),"+f"(c[2]),"+f"(c[3])
                 :"r"(a[0]),"r"(a[1]),"r"(a[2]),"r"(a[3]),"r"(b[0]),"r"(b[1]));
}
__device__ __forceinline__ void cpa16(unsigned d, const void* s){
    asm volatile("cp.async.cg.shared.global [%0],[%1],16;"::"r"(d),"l"(s):"memory");
}
__device__ __forceinline__ void cpcommit(){ asm volatile("cp.async.commit_group;":::"memory"); }
__device__ __forceinline__ float ex2f(float x){
    float r; asm("ex2.approx.ftz.f32 %0,%1;":"=f"(r):"f"(x)); return r;
}
__device__ __forceinline__ void mbar_init(unsigned a,unsigned c){
    asm volatile("mbarrier.init.shared.b64 [%0],%1;"::"r"(a),"r"(c):"memory");
}
__device__ __forceinline__ void mbar_expect(unsigned a,unsigned b){
    asm volatile("mbarrier.arrive.expect_tx.shared.b64 _,[%0],%1;"::"r"(a),"r"(b):"memory");
}
__device__ __forceinline__ void mbar_wait(unsigned a,unsigned p){
    asm volatile("{\n\t.reg .pred P;\nW_%=:\n\t"
                 "mbarrier.try_wait.parity.acquire.cta.shared::cta.b64 P,[%0],%1;\n\t"
                 "@!P bra W_%=;\n\t}"::"r"(a),"r"(p):"memory");
}
__device__ __forceinline__ void tma2(unsigned s,const CUtensorMap* m,int cx,int cy,unsigned mb){
    asm volatile("cp.async.bulk.tensor.2d.shared::cta.global.tile.mbarrier::complete_tx::bytes "
                 "[%0],[%1,{%2,%3}],[%4];"
                 ::"r"(s),"l"(m),"r"(cx),"r"(cy),"r"(mb):"memory");
}

// ---------------------------------------------------------------------------
// TMA-fed fp16 GEMM: C = A[M][2048] @ B[N][2048]^T, 1 MMA per k16.
// CTA 128x128, K-chunk 64, 4 stages x 32KB (3 prefetches in flight), SW128.
// ---------------------------------------------------------------------------
#define GSMEM (1024 + 4*32768)

__global__ void __launch_bounds__(256,1)
gemm_tma(const __grid_constant__ CUtensorMap tA,
         const __grid_constant__ CUtensorMap tB,
         float* __restrict__ Cf,
         __half* __restrict__ q1, __half* __restrict__ k1, __half* __restrict__ v1){
    extern __shared__ char smraw[];
    unsigned smu; asm("{ .reg .u64 t; cvta.to.shared.u64 t,%1; cvt.u32.u64 %0,t; }":"=r"(smu):"l"(smraw));
    const unsigned base = (smu + 1023u) & ~1023u;
    const unsigned tiles = base + 1024;
    const int tid = threadIdx.x, lane = tid & 31, wid = tid >> 5;
    const int wm = wid >> 1, wn = wid & 1;
    const int bm = blockIdx.y * 128, bn = blockIdx.x * 128;

    if(tid==0)
#pragma unroll
        for(int s=0;s<4;s++) mbar_init(base + 8u*s, 1);
    __syncthreads();

    auto issue = [&](int s, int k0){
        unsigned mb = base + 8u*(unsigned)s;
        mbar_expect(mb, 32768u);
        unsigned dst = tiles + (unsigned)s*32768u;
        tma2(dst,          &tA, k0, bm, mb);
        tma2(dst + 16384u, &tB, k0, bn, mb);
    };
    if(tid==0){ issue(0,0); issue(1,64); issue(2,128); }

    float acc[2][8][4];
#pragma unroll
    for(int i=0;i<2;i++)
#pragma unroll
        for(int j=0;j<8;j++)
#pragma unroll
            for(int q=0;q<4;q++) acc[i][j][q]=0.f;

    unsigned arow[2], axor[2], brow[4], bxor[4];
#pragma unroll
    for(int mf=0;mf<2;mf++){
        int r = wm*32 + mf*16 + (lane&7) + ((lane>>3)&1)*8;
        arow[mf] = (unsigned)(r*128); axor[mf] = (unsigned)((r&7)<<4);
    }
#pragma unroll
    for(int jj=0;jj<4;jj++){
        int r = wn*64 + jj*16 + (lane&7) + (lane>>4)*8;
        brow[jj] = (unsigned)(r*128); bxor[jj] = (unsigned)((r&7)<<4);
    }
    const unsigned acol = (unsigned)((lane>>4)*16);
    const unsigned bcol = (unsigned)(((lane>>3)&1)*16);

    int ph[4] = {0,0,0,0};
    for(int it=0; it<32; ++it){
        int s = it & 3;
        mbar_wait(base + 8u*s, ph[s]); ph[s] ^= 1;
        unsigned sb = tiles + (unsigned)s*32768u;
#pragma unroll
        for(int ks=0;ks<4;ks++){
            unsigned ah[2][4], bh[4][4];
#pragma unroll
            for(int mf=0;mf<2;mf++){
                unsigned c = (acol + ks*32);
                ldsm4(ah[mf], sb + arow[mf] + (c ^ axor[mf]));
            }
#pragma unroll
            for(int jj=0;jj<4;jj++){
                unsigned c = (bcol + ks*32);
                ldsm4(bh[jj], sb + 16384u + brow[jj] + (c ^ bxor[jj]));
            }
#pragma unroll
            for(int mf=0;mf<2;mf++)
#pragma unroll
                for(int nf=0;nf<8;nf++)
                    mmaf16(acc[mf][nf], ah[mf], &bh[nf>>1][(nf&1)*2]);
        }
        __syncthreads();
        if(it+3 < 32 && tid==0) issue((it+3)&3, (it+3)*64);
    }

    const int r0 = bm + wm*32 + (lane>>2);
    if(Cf){
        const int c0 = bn + wn*64 + (lane&3)*2;
#pragma unroll
        for(int mf=0;mf<2;mf++)
#pragma unroll
            for(int nf=0;nf<8;nf++){
                float* p0 = Cf + (size_t)(r0 + mf*16)*2048 + c0 + nf*8;
                float* p1 = Cf + (size_t)(r0 + mf*16 + 8)*2048 + c0 + nf*8;
                *(float2*)p0 = make_float2(acc[mf][nf][0], acc[mf][nf][1]);
                *(float2*)p1 = make_float2(acc[mf][nf][2], acc[mf][nf][3]);
            }
    } else {
        __half* O; int No, cbase; float scl;
        if(bn < 2048){ O=q1; No=2048; scl=QSCALE; cbase=bn; }
        else if(bn < 2560){ O=k1; No=512; scl=1.f; cbase=bn-2048; }
        else { O=v1; No=512; scl=1.f; cbase=bn-2560; }
        const int c0 = cbase + wn*64 + (lane&3)*2;
#pragma unroll
        for(int mf=0;mf<2;mf++)
#pragma unroll
            for(int nf=0;nf<8;nf++)
#pragma unroll
                for(int hl=0;hl<2;hl++){
                    size_t idx = (size_t)(r0 + mf*16 + hl*8)*No + c0 + nf*8;
                    *(unsigned*)(O + idx) =
                        packhf(acc[mf][nf][hl*2]*scl, acc[mf][nf][hl*2+1]*scl);
                }
    }
}

// ---------------------------------------------------------------------------
// fp16 flash attention: q-tile 64, kv-tile 64, 3-stage cp.async, 3 CTAs/SM.
// ---------------------------------------------------------------------------
#define ASTR 72
#define A_Q  (64*ASTR)
#define A_MS (64*ASTR)
#define A_SS (2*A_MS)
#define ASMEM ((A_Q + 3*A_SS)*2)   // 64512 B

__global__ void __launch_bounds__(128,3)
attn_mma(const __half* __restrict__ Q1, const __half* __restrict__ K1,
         const __half* __restrict__ V1, __half* __restrict__ C1){
    extern __shared__ __half sm[];
    const unsigned smb = (unsigned)__cvta_generic_to_shared(sm);
    const int tid = threadIdx.x, lane = tid&31, wid = tid>>5;
    const int qt = blockIdx.x, bh = blockIdx.y;
    const int b = bh>>5, h = bh&31, kvh = h>>2;
    const int qbase = b*2048 + qt*64;
    const int kbase0 = b*2048;
    const int kvcol = kvh*64;

    // Q tile
#pragma unroll
    for(int t=0;t<4;t++){
        int c = tid + t*128;
        int row = c>>3, ch = c&7;
        const __half* src = Q1 + (size_t)(qbase+row)*2048 + h*64 + ch*8;
        unsigned dst = smb + (unsigned)((row*ASTR)*2 + ch*16);
        cpa16(dst, src);
    }
    cpcommit();

    auto load_kv = [&](int s, int kt){
#pragma unroll
        for(int t=0;t<8;t++){
            int c = tid + t*128;
            int mat = c>>9, idx = c&511;
            int row = idx>>3, ch = idx&7;
            const __half* src = (mat ? V1 : K1) + (size_t)(kbase0 + kt*64 + row)*512 + kvcol + ch*8;
            unsigned dst = smb + (unsigned)((A_Q + s*A_SS + mat*A_MS + row*ASTR)*2 + ch*16);
            cpa16(dst, src);
        }
        cpcommit();
    };
    load_kv(0, 0);
    load_kv(1, 1);
    load_kv(2, 2);

    // groups pending: Q, kv0, kv1, kv2 -> allow 3 pending => Q complete
    asm volatile("cp.async.wait_group 3;":::"memory");
    __syncthreads();

    unsigned aq[4][4];
    const unsigned qro = (unsigned)(((wid*16 + (lane&15))*ASTR)*2 + (lane>>4)*16);
#pragma unroll
    for(int ks=0;ks<4;ks++) ldsm4(aq[ks], smb + qro + ks*32);

    float od[8][4];
#pragma unroll
    for(int nf=0;nf<8;nf++)
#pragma unroll
        for(int q=0;q<4;q++) od[nf][q]=0.f;
    float l0=0.f, l1=0.f;

    const unsigned bro_col = (unsigned)(((lane>>3)&1)*16);
    const unsigned bro_row = (unsigned)((lane&7) + (lane>>4)*8);
    const unsigned tro_row = (unsigned)((lane&7) + ((lane>>3)&1)*8);
    const unsigned tro_col = (unsigned)((lane>>4)*16);

    int slot = 0;
    for(int kt=0;kt<32;kt++){
        // kv(kt) must be complete; kv(kt+1), kv(kt+2) may be pending
        asm volatile("cp.async.wait_group 2;":::"memory");
        __syncthreads();
        unsigned sb = smb + (unsigned)((A_Q + slot*A_SS)*2);

        float sc[8][4];
#pragma unroll
        for(int nf=0;nf<8;nf++)
#pragma unroll
            for(int q=0;q<4;q++) sc[nf][q]=0.f;

#pragma unroll
        for(int ks=0;ks<4;ks++){
#pragma unroll
            for(int ng=0;ng<4;ng++){
                unsigned kh4[4];
                unsigned ro = (unsigned)((ng*16 + bro_row)*ASTR*2) + bro_col + ks*32;
                ldsm4(kh4, sb + ro);
                mmaf16(sc[ng*2+0], aq[ks], &kh4[0]);
                mmaf16(sc[ng*2+1], aq[ks], &kh4[2]);
            }
        }

#pragma unroll
        for(int ks=0;ks<4;ks++){
            unsigned aph[4];
#pragma unroll
            for(int q=0;q<4;q++){
                int nf = ks*2 + (q>>1);
                float v0 = ex2f(sc[nf][(q&1)*2]);
                float v1 = ex2f(sc[nf][(q&1)*2+1]);
                if(q&1) l1 += v0 + v1; else l0 += v0 + v1;
                aph[q] = packhf(v0, v1);
            }
#pragma unroll
            for(int dg=0;dg<4;dg++){
                unsigned vh4[4];
                unsigned ro = (unsigned)((ks*16 + tro_row)*ASTR*2) + dg*32 + tro_col;
                ldsm4t(vh4, sb + (unsigned)(A_MS*2) + ro);
                mmaf16(od[dg*2+0], aph, &vh4[0]);
                mmaf16(od[dg*2+1], aph, &vh4[2]);
            }
        }

        __syncthreads();
        if(kt+3 < 32) load_kv(slot, kt+3); else cpcommit();
        slot = (slot+1 == 3) ? 0 : slot+1;
    }

    l0 += __shfl_xor_sync(0xffffffffu, l0, 1);
    l0 += __shfl_xor_sync(0xffffffffu, l0, 2);
    l1 += __shfl_xor_sync(0xffffffffu, l1, 1);
    l1 += __shfl_xor_sync(0xffffffffu, l1, 2);
    float inv0 = 1.f/l0, inv1 = 1.f/l1;
    const int r = lane>>2, cb = (lane&3)*2;
    size_t i0 = (size_t)(qbase + wid*16 + r)*2048 + h*64 + cb;
    size_t i1 = i0 + (size_t)8*2048;
#pragma unroll
    for(int nf=0;nf<8;nf++){
        *(unsigned*)(C1 + i0 + nf*8) = packhf(od[nf][0]*inv0, od[nf][1]*inv0);
        *(unsigned*)(C1 + i1 + nf*8) = packhf(od[nf][2]*inv1, od[nf][3]*inv1);
    }
}

// ---- host ----
typedef CUresult (*tmap_fn_t)(CUtensorMap*, CUtensorMapDataType, cuuint32_t, void*,
                              const cuuint64_t*, const cuuint64_t*, const cuuint32_t*, const cuuint32_t*,
                              CUtensorMapInterleave, CUtensorMapSwizzle, CUtensorMapL2promotion, CUtensorMapFloatOOBfill);

static void make2d(tmap_fn_t enc, CUtensorMap* m, void* ptr, cuuint64_t rows){
    cuuint64_t dims[2] = {2048ull, rows};
    cuuint64_t strd[1] = {4096ull};
    cuuint32_t box[2] = {64u, 128u};
    cuuint32_t es[2] = {1u, 1u};
    enc(m, CU_TENSOR_MAP_DATA_TYPE_FLOAT16, 2, ptr, dims, strd, box, es,
        CU_TENSOR_MAP_INTERLEAVE_NONE, CU_TENSOR_MAP_SWIZZLE_128B,
        CU_TENSOR_MAP_L2_PROMOTION_L2_128B, CU_TENSOR_MAP_FLOAT_OOB_FILL_NONE);
}

extern "C" void kernel_launch(void* const* d_in, const int* in_sizes, int n_in,
                              void* d_out, int out_size){
    const float* x  = (const float*)d_in[0];
    const float* Wq = (const float*)d_in[1];
    const float* Wk = (const float*)d_in[2];
    const float* Wv = (const float*)d_in[3];
    const float* Wo = (const float*)d_in[4];
    float* out = (float*)d_out;

    void *xb,*wb,*wob,*q1,*k1,*v1;
    cudaGetSymbolAddress(&xb,g_x);
    cudaGetSymbolAddress(&wb,g_w);
    cudaGetSymbolAddress(&wob,g_wo);
    cudaGetSymbolAddress(&q1,g_q);
    cudaGetSymbolAddress(&k1,g_k);
    cudaGetSymbolAddress(&v1,g_v);

    tmap_fn_t enc = 0;
    cudaDriverEntryPointQueryResult qr;
    cudaGetDriverEntryPointByVersion("cuTensorMapEncodeTiled", (void**)&enc, 12000,
                                     cudaEnableDefault, &qr);

    static CUtensorMap tX,tW,tWo;
    make2d(enc,&tX,xb,4096);
    make2d(enc,&tW,wb,3072);
    make2d(enc,&tWo,wob,2048);

    cudaFuncSetAttribute(gemm_tma, cudaFuncAttributeMaxDynamicSharedMemorySize, GSMEM);
    cudaFuncSetAttribute(attn_mma, cudaFuncAttributeMaxDynamicSharedMemorySize, ASMEM);

    wtruncAll<<<dim3(160,64),dim3(32,8)>>>(Wq, Wk, Wv, Wo, (__half*)wb, (__half*)wob);
    ftrunc<<<512,256>>>((const float4*)x, (uint2*)xb, 4096*2048/4);

    // fused QKV projection
    gemm_tma<<<dim3(24,32),256,GSMEM>>>(tX,tW, nullptr,
        (__half*)q1, (__half*)k1, (__half*)v1);

    // attention -> ctx (reuse g_x)
    attn_mma<<<dim3(32,64),128,ASMEM>>>((__half*)q1, (__half*)k1, (__half*)v1, (__half*)xb);

    // O projection -> fp32 out
    gemm_tma<<<dim3(16,32),256,GSMEM>>>(tX,tWo, out, nullptr,nullptr,nullptr);
}

// round 17
// speedup vs baseline: 1.1496x; 1.1496x over previous
#include <cuda_runtime.h>
#include <cuda.h>
#include <cuda_fp16.h>
#include <math.h>

// ---- scratch (fp16) ----
__device__ __half g_x[4096*2048];                 // x trunc; reused for ctx
__device__ __half g_w[3072*2048];                 // concat WqT|WkT|WvT trunc
__device__ __half g_wo[2048*2048];
__device__ __half g_q[4096*2048];
__device__ __half g_k[4096*512];
__device__ __half g_v[4096*512];

#define QSCALE (0.125f * 1.4426950408889634f)   // 1/sqrt(64) * log2(e)

__device__ __forceinline__ unsigned packhf(float lo, float hi){
    unsigned r; asm("cvt.rn.f16x2.f32 %0, %1, %2;":"=r"(r):"f"(hi),"f"(lo)); return r;
}

// fp32 -> fp16 truncate
__global__ void __launch_bounds__(256) ftrunc(const float4* __restrict__ in,
                                              uint2* __restrict__ out, int n4){
    int i = blockIdx.x*blockDim.x + threadIdx.x, st = gridDim.x*blockDim.x;
    for(; i < n4; i += st){
        float4 v = in[i];
        uint2 o;
        o.x = packhf(v.x, v.y);
        o.y = packhf(v.z, v.w);
        out[i] = o;
    }
}

// all 4 weights: transpose + fp16 truncate, one launch
__global__ void wtruncAll(const float* __restrict__ Wq, const float* __restrict__ Wk,
                          const float* __restrict__ Wv, const float* __restrict__ Wo,
                          __half* __restrict__ qkv, __half* __restrict__ wo){
    __shared__ float t[32][33];
    int bx = blockIdx.x;
    const float* W; __half *T; int N, n0;
    if(bx < 64){ W=Wq; T=qkv; N=2048; n0=bx*32; }
    else if(bx < 80){ W=Wk; T=qkv+(size_t)2048*2048; N=512; n0=(bx-64)*32; }
    else if(bx < 96){ W=Wv; T=qkv+(size_t)2560*2048; N=512; n0=(bx-80)*32; }
    else { W=Wo; T=wo; N=2048; n0=(bx-96)*32; }
    int k0 = blockIdx.y*32;
    int tx = threadIdx.x, ty = threadIdx.y;
#pragma unroll
    for(int p=0;p<32;p+=8) t[ty+p][tx] = W[(size_t)(k0+ty+p)*N + n0+tx];
    __syncthreads();
#pragma unroll
    for(int p=0;p<32;p+=8)
        T[(size_t)(n0+ty+p)*2048 + k0+tx] = __float2half_rn(t[tx][ty+p]);
}

// ---- helpers ----
__device__ __forceinline__ void ldsm4(unsigned* r, unsigned a){
    asm volatile("ldmatrix.sync.aligned.m8n8.x4.shared.b16 {%0,%1,%2,%3},[%4];"
                 :"=r"(r[0]),"=r"(r[1]),"=r"(r[2]),"=r"(r[3]):"r"(a));
}
__device__ __forceinline__ void ldsm4t(unsigned* r, unsigned a){
    asm volatile("ldmatrix.sync.aligned.m8n8.x4.trans.shared.b16 {%0,%1,%2,%3},[%4];"
                 :"=r"(r[0]),"=r"(r[1]),"=r"(r[2]),"=r"(r[3]):"r"(a));
}
__device__ __forceinline__ void mmaf16(float* c, const unsigned* a, const unsigned* b){
    asm volatile("mma.sync.aligned.m16n8k16.row.col.f32.f16.f16.f32 "
                 "{%0,%1,%2,%3},{%4,%5,%6,%7},{%8,%9},{%0,%1,%2,%3};"
                 :"+f"(c[0]),"+f"(c[1]),"+f"(c[2]),"+f"(c[3])
                 :"r"(a[0]),"r"(a[1]),"r"(a[2]),"r"(a[3]),"r"(b[0]),"r"(b[1]));
}
__device__ __forceinline__ void cpa16(unsigned d, const void* s){
    asm volatile("cp.async.cg.shared.global [%0],[%1],16;"::"r"(d),"l"(s):"memory");
}
__device__ __forceinline__ void cpcommit(){ asm volatile("cp.async.commit_group;":::"memory"); }
__device__ __forceinline__ float ex2f(float x){
    float r; asm("ex2.approx.ftz.f32 %0,%1;":"=f"(r):"f"(x)); return r;
}
__device__ __forceinline__ void mbar_init(unsigned a,unsigned c){
    asm volatile("mbarrier.init.shared.b64 [%0],%1;"::"r"(a),"r"(c):"memory");
}
__device__ __forceinline__ void mbar_expect(unsigned a,unsigned b){
    asm volatile("mbarrier.arrive.expect_tx.shared.b64 _,[%0],%1;"::"r"(a),"r"(b):"memory");
}
__device__ __forceinline__ void mbar_wait(unsigned a,unsigned p){
    asm volatile("{\n\t.reg .pred P;\nW_%=:\n\t"
                 "mbarrier.try_wait.parity.acquire.cta.shared::cta.b64 P,[%0],%1;\n\t"
                 "@!P bra W_%=;\n\t}"::"r"(a),"r"(p):"memory");
}
__device__ __forceinline__ void tma2(unsigned s,const CUtensorMap* m,int cx,int cy,unsigned mb){
    asm volatile("cp.async.bulk.tensor.2d.shared::cta.global.tile.mbarrier::complete_tx::bytes "
                 "[%0],[%1,{%2,%3}],[%4];"
                 ::"r"(s),"l"(m),"r"(cx),"r"(cy),"r"(mb):"memory");
}

// ---------------------------------------------------------------------------
// TMA-fed fp16 GEMM: CTA tile 256x128, warp tile 64x64 (16 MACs/smem-byte).
// 8 warps (4x2). K-chunk 64, 2 stages x 48KB, SW128.
// ---------------------------------------------------------------------------
#define GSMEM (1024 + 2*49152)

__global__ void __launch_bounds__(256,1)
gemm_tma(const __grid_constant__ CUtensorMap tA,
         const __grid_constant__ CUtensorMap tB,
         float* __restrict__ Cf,
         __half* __restrict__ q1, __half* __restrict__ k1, __half* __restrict__ v1){
    extern __shared__ char smraw[];
    unsigned smu; asm("{ .reg .u64 t; cvta.to.shared.u64 t,%1; cvt.u32.u64 %0,t; }":"=r"(smu):"l"(smraw));
    const unsigned base = (smu + 1023u) & ~1023u;
    const unsigned tiles = base + 1024;
    const int tid = threadIdx.x, lane = tid & 31, wid = tid >> 5;
    const int wm = wid >> 1, wn = wid & 1;
    const int bm = blockIdx.y * 256, bn = blockIdx.x * 128;

    if(tid==0){ mbar_init(base,1); mbar_init(base+8,1); }
    __syncthreads();

    auto issue = [&](int s, int k0){
        unsigned mb = base + 8u*(unsigned)s;
        mbar_expect(mb, 49152u);
        unsigned dst = tiles + (unsigned)s*49152u;
        tma2(dst,          &tA, k0, bm,       mb);
        tma2(dst + 16384u, &tA, k0, bm + 128, mb);
        tma2(dst + 32768u, &tB, k0, bn,       mb);
    };
    if(tid==0){ issue(0,0); issue(1,64); }

    float acc[4][8][4];
#pragma unroll
    for(int i=0;i<4;i++)
#pragma unroll
        for(int j=0;j<8;j++)
#pragma unroll
            for(int q=0;q<4;q++) acc[i][j][q]=0.f;

    unsigned arow[4], axor[4], brow[4], bxor[4];
#pragma unroll
    for(int mf=0;mf<4;mf++){
        int r = wm*64 + mf*16 + (lane&7) + ((lane>>3)&1)*8;
        arow[mf] = (unsigned)(r*128); axor[mf] = (unsigned)((r&7)<<4);
    }
#pragma unroll
    for(int jj=0;jj<4;jj++){
        int r = wn*64 + jj*16 + (lane&7) + (lane>>4)*8;
        brow[jj] = (unsigned)(r*128); bxor[jj] = (unsigned)((r&7)<<4);
    }
    const unsigned acol = (unsigned)((lane>>4)*16);
    const unsigned bcol = (unsigned)(((lane>>3)&1)*16);

    int ph[2] = {0,0};
    for(int it=0; it<32; ++it){
        int s = it & 1;
        mbar_wait(base + 8u*s, ph[s]); ph[s] ^= 1;
        unsigned sb = tiles + (unsigned)s*49152u;
#pragma unroll
        for(int ks=0;ks<4;ks++){
            unsigned ah[4][4], bh[4][4];
#pragma unroll
            for(int mf=0;mf<4;mf++){
                unsigned c = (acol + ks*32);
                ldsm4(ah[mf], sb + arow[mf] + (c ^ axor[mf]));
            }
#pragma unroll
            for(int jj=0;jj<4;jj++){
                unsigned c = (bcol + ks*32);
                ldsm4(bh[jj], sb + 32768u + brow[jj] + (c ^ bxor[jj]));
            }
#pragma unroll
            for(int mf=0;mf<4;mf++)
#pragma unroll
                for(int nf=0;nf<8;nf++)
                    mmaf16(acc[mf][nf], ah[mf], &bh[nf>>1][(nf&1)*2]);
        }
        __syncthreads();
        if(it+2 < 32 && tid==0) issue(s, (it+2)*64);
    }

    const int r0 = bm + wm*64 + (lane>>2);
    if(Cf){
        const int c0 = bn + wn*64 + (lane&3)*2;
#pragma unroll
        for(int mf=0;mf<4;mf++)
#pragma unroll
            for(int nf=0;nf<8;nf++){
                float* p0 = Cf + (size_t)(r0 + mf*16)*2048 + c0 + nf*8;
                float* p1 = Cf + (size_t)(r0 + mf*16 + 8)*2048 + c0 + nf*8;
                *(float2*)p0 = make_float2(acc[mf][nf][0], acc[mf][nf][1]);
                *(float2*)p1 = make_float2(acc[mf][nf][2], acc[mf][nf][3]);
            }
    } else {
        __half* O; int No, cbase; float scl;
        if(bn < 2048){ O=q1; No=2048; scl=QSCALE; cbase=bn; }
        else if(bn < 2560){ O=k1; No=512; scl=1.f; cbase=bn-2048; }
        else { O=v1; No=512; scl=1.f; cbase=bn-2560; }
        const int c0 = cbase + wn*64 + (lane&3)*2;
#pragma unroll
        for(int mf=0;mf<4;mf++)
#pragma unroll
            for(int nf=0;nf<8;nf++)
#pragma unroll
                for(int hl=0;hl<2;hl++){
                    size_t idx = (size_t)(r0 + mf*16 + hl*8)*No + c0 + nf*8;
                    *(unsigned*)(O + idx) =
                        packhf(acc[mf][nf][hl*2]*scl, acc[mf][nf][hl*2+1]*scl);
                }
    }
}

// ---------------------------------------------------------------------------
// fp16 flash attention: CTA = 128 q rows, 4 warps x 32 q-rows (16 MACs/B),
// kv-tile 64, 3-stage cp.async, 2 CTAs/SM.
// ---------------------------------------------------------------------------
#define ASTR 72
#define A_Q  (128*ASTR)
#define A_MS (64*ASTR)
#define A_SS (2*A_MS)
#define ASMEM ((A_Q + 3*A_SS)*2)   // 73728 B

__global__ void __launch_bounds__(128,2)
attn_mma(const __half* __restrict__ Q1, const __half* __restrict__ K1,
         const __half* __restrict__ V1, __half* __restrict__ C1){
    extern __shared__ __half sm[];
    const unsigned smb = (unsigned)__cvta_generic_to_shared(sm);
    const int tid = threadIdx.x, lane = tid&31, wid = tid>>5;
    const int qt = blockIdx.x, bh = blockIdx.y;
    const int b = bh>>5, h = bh&31, kvh = h>>2;
    const int qbase = b*2048 + qt*128;
    const int kbase0 = b*2048;
    const int kvcol = kvh*64;

    // Q tile: 128 rows x 64 cols = 1024 chunks / 128 thr = 8 iters
#pragma unroll
    for(int t=0;t<8;t++){
        int c = tid + t*128;
        int row = c>>3, ch = c&7;
        const __half* src = Q1 + (size_t)(qbase+row)*2048 + h*64 + ch*8;
        unsigned dst = smb + (unsigned)((row*ASTR)*2 + ch*16);
        cpa16(dst, src);
    }
    cpcommit();

    auto load_kv = [&](int s, int kt){
#pragma unroll
        for(int t=0;t<8;t++){
            int c = tid + t*128;
            int mat = c>>9, idx = c&511;
            int row = idx>>3, ch = idx&7;
            const __half* src = (mat ? V1 : K1) + (size_t)(kbase0 + kt*64 + row)*512 + kvcol + ch*8;
            unsigned dst = smb + (unsigned)((A_Q + s*A_SS + mat*A_MS + row*ASTR)*2 + ch*16);
            cpa16(dst, src);
        }
        cpcommit();
    };
    load_kv(0, 0);
    load_kv(1, 1);
    load_kv(2, 2);

    asm volatile("cp.async.wait_group 3;":::"memory");
    __syncthreads();

    // Q fragments: 2 mf x 4 ks (persistent)
    unsigned aq[2][4][4];
#pragma unroll
    for(int mf=0;mf<2;mf++){
        unsigned qro = (unsigned)(((wid*32 + mf*16 + (lane&15))*ASTR)*2 + (lane>>4)*16);
#pragma unroll
        for(int ks=0;ks<4;ks++) ldsm4(aq[mf][ks], smb + qro + ks*32);
    }

    float od[2][8][4];
#pragma unroll
    for(int mf=0;mf<2;mf++)
#pragma unroll
        for(int nf=0;nf<8;nf++)
#pragma unroll
            for(int q=0;q<4;q++) od[mf][nf][q]=0.f;
    float l[2][2] = {{0.f,0.f},{0.f,0.f}};

    const unsigned bro_col = (unsigned)(((lane>>3)&1)*16);
    const unsigned bro_row = (unsigned)((lane&7) + (lane>>4)*8);
    const unsigned tro_row = (unsigned)((lane&7) + ((lane>>3)&1)*8);
    const unsigned tro_col = (unsigned)((lane>>4)*16);

    int slot = 0;
    for(int kt=0;kt<32;kt++){
        asm volatile("cp.async.wait_group 2;":::"memory");
        __syncthreads();
        unsigned sb = smb + (unsigned)((A_Q + slot*A_SS)*2);

        float sc[2][8][4];
#pragma unroll
        for(int mf=0;mf<2;mf++)
#pragma unroll
            for(int nf=0;nf<8;nf++)
#pragma unroll
                for(int q=0;q<4;q++) sc[mf][nf][q]=0.f;

        // QK: per ks per ng: 1 K-ldsm feeds 4 MMAs (2 mf x 2 hf)
#pragma unroll
        for(int ks=0;ks<4;ks++){
#pragma unroll
            for(int ng=0;ng<4;ng++){
                unsigned kh4[4];
                unsigned ro = (unsigned)((ng*16 + bro_row)*ASTR*2) + bro_col + ks*32;
                ldsm4(kh4, sb + ro);
#pragma unroll
                for(int mf=0;mf<2;mf++){
                    mmaf16(sc[mf][ng*2+0], aq[mf][ks], &kh4[0]);
                    mmaf16(sc[mf][ng*2+1], aq[mf][ks], &kh4[2]);
                }
            }
        }

        // PV: per ks: exp+pack both mf, then per dg: 1 V-ldsm feeds 4 MMAs
#pragma unroll
        for(int ks=0;ks<4;ks++){
            unsigned aph[2][4];
#pragma unroll
            for(int mf=0;mf<2;mf++)
#pragma unroll
                for(int q=0;q<4;q++){
                    int nf = ks*2 + (q>>1);
                    float v0 = ex2f(sc[mf][nf][(q&1)*2]);
                    float v1 = ex2f(sc[mf][nf][(q&1)*2+1]);
                    l[mf][q&1] += v0 + v1;
                    aph[mf][q] = packhf(v0, v1);
                }
#pragma unroll
            for(int dg=0;dg<4;dg++){
                unsigned vh4[4];
                unsigned ro = (unsigned)((ks*16 + tro_row)*ASTR*2) + dg*32 + tro_col;
                ldsm4t(vh4, sb + (unsigned)(A_MS*2) + ro);
#pragma unroll
                for(int mf=0;mf<2;mf++){
                    mmaf16(od[mf][dg*2+0], aph[mf], &vh4[0]);
                    mmaf16(od[mf][dg*2+1], aph[mf], &vh4[2]);
                }
            }
        }

        __syncthreads();
        if(kt+3 < 32) load_kv(slot, kt+3); else cpcommit();
        slot = (slot+1 == 3) ? 0 : slot+1;
    }

    // final l reduce + write
#pragma unroll
    for(int mf=0;mf<2;mf++)
#pragma unroll
        for(int hl=0;hl<2;hl++){
            l[mf][hl] += __shfl_xor_sync(0xffffffffu, l[mf][hl], 1);
            l[mf][hl] += __shfl_xor_sync(0xffffffffu, l[mf][hl], 2);
        }
    const int r = lane>>2, cb = (lane&3)*2;
#pragma unroll
    for(int mf=0;mf<2;mf++){
        float inv0 = 1.f/l[mf][0], inv1 = 1.f/l[mf][1];
        size_t i0 = (size_t)(qbase + wid*32 + mf*16 + r)*2048 + h*64 + cb;
        size_t i1 = i0 + (size_t)8*2048;
#pragma unroll
        for(int nf=0;nf<8;nf++){
            *(unsigned*)(C1 + i0 + nf*8) = packhf(od[mf][nf][0]*inv0, od[mf][nf][1]*inv0);
            *(unsigned*)(C1 + i1 + nf*8) = packhf(od[mf][nf][2]*inv1, od[mf][nf][3]*inv1);
        }
    }
}

// ---- host ----
typedef CUresult (*tmap_fn_t)(CUtensorMap*, CUtensorMapDataType, cuuint32_t, void*,
                              const cuuint64_t*, const cuuint64_t*, const cuuint32_t*, const cuuint32_t*,
                              CUtensorMapInterleave, CUtensorMapSwizzle, CUtensorMapL2promotion, CUtensorMapFloatOOBfill);

static void make2d(tmap_fn_t enc, CUtensorMap* m, void* ptr, cuuint64_t rows){
    cuuint64_t dims[2] = {2048ull, rows};
    cuuint64_t strd[1] = {4096ull};
    cuuint32_t box[2] = {64u, 128u};
    cuuint32_t es[2] = {1u, 1u};
    enc(m, CU_TENSOR_MAP_DATA_TYPE_FLOAT16, 2, ptr, dims, strd, box, es,
        CU_TENSOR_MAP_INTERLEAVE_NONE, CU_TENSOR_MAP_SWIZZLE_128B,
        CU_TENSOR_MAP_L2_PROMOTION_L2_128B, CU_TENSOR_MAP_FLOAT_OOB_FILL_NONE);
}

extern "C" void kernel_launch(void* const* d_in, const int* in_sizes, int n_in,
                              void* d_out, int out_size){
    const float* x  = (const float*)d_in[0];
    const float* Wq = (const float*)d_in[1];
    const float* Wk = (const float*)d_in[2];
    const float* Wv = (const float*)d_in[3];
    const float* Wo = (const float*)d_in[4];
    float* out = (float*)d_out;

    void *xb,*wb,*wob,*q1,*k1,*v1;
    cudaGetSymbolAddress(&xb,g_x);
    cudaGetSymbolAddress(&wb,g_w);
    cudaGetSymbolAddress(&wob,g_wo);
    cudaGetSymbolAddress(&q1,g_q);
    cudaGetSymbolAddress(&k1,g_k);
    cudaGetSymbolAddress(&v1,g_v);

    tmap_fn_t enc = 0;
    cudaDriverEntryPointQueryResult qr;
    cudaGetDriverEntryPointByVersion("cuTensorMapEncodeTiled", (void**)&enc, 12000,
                                     cudaEnableDefault, &qr);

    static CUtensorMap tX,tW,tWo;
    make2d(enc,&tX,xb,4096);
    make2d(enc,&tW,wb,3072);
    make2d(enc,&tWo,wob,2048);

    cudaFuncSetAttribute(gemm_tma, cudaFuncAttributeMaxDynamicSharedMemorySize, GSMEM);
    cudaFuncSetAttribute(attn_mma, cudaFuncAttributeMaxDynamicSharedMemorySize, ASMEM);

    wtruncAll<<<dim3(160,64),dim3(32,8)>>>(Wq, Wk, Wv, Wo, (__half*)wb, (__half*)wob);
    ftrunc<<<512,256>>>((const float4*)x, (uint2*)xb, 4096*2048/4);

    // fused QKV projection: M=4096 (16 tiles of 256), N=3072 (24 tiles of 128)
    gemm_tma<<<dim3(24,16),256,GSMEM>>>(tX,tW, nullptr,
        (__half*)q1, (__half*)k1, (__half*)v1);

    // attention -> ctx (reuse g_x)
    attn_mma<<<dim3(16,64),128,ASMEM>>>((__half*)q1, (__half*)k1, (__half*)v1, (__half*)xb);

    // O projection -> fp32 out
    gemm_tma<<<dim3(16,16),256,GSMEM>>>(tX,tWo, out, nullptr,nullptr,nullptr);
}